// round 6
// baseline (speedup 1.0000x reference)
#include <cuda_runtime.h>
#include <cuda_fp16.h>
#include <cuda_bf16.h>
#include <cstdint>
#include <math.h>

#define MAXN 100000
#define MAXE 1600000
#define FD   128      // IN == HID == 128
#define OUTC 64

// ---------------- scratch (device globals; no allocation allowed) ----------
__device__ __half g_bufH[MAXN * FD];  // fp16 GEMM outputs (U, then V)
__device__ float  g_bufA[MAXN * FD];  // fp32 h (layer-1 output)
__device__ int    g_cnt[MAXN];
__device__ int    g_rowptr[MAXN + 1];
__device__ int    g_cursor[MAXN];
__device__ int    g_csr[MAXE];
__device__ float  g_dinv[MAXN];
__device__ unsigned long long g_status[512];   // lookback: (flag<<32)|value
__device__ unsigned int g_ticket;

// ---------------- zero / init ----------------------------------------------
__global__ void k_zero(int n) {
    int i = blockIdx.x * blockDim.x + threadIdx.x;
    if (i < n) g_cnt[i] = 0;
    if (i < 512) g_status[i] = 0ULL;
    if (i == 0) g_ticket = 0u;
}

// ---------------- single-pass scan (decoupled lookback) ---------------------
// one item per thread, 256/block; virtual block id via ticket keeps
// lookback ordering aligned with data mapping. Also writes rowptr/cursor/dinv.
__global__ void k_scan_lb(int n) {
    __shared__ int s_vbid;
    __shared__ int s_excl;
    __shared__ int wsum[8], woff[8];
    int tid = threadIdx.x, lane = tid & 31, w = tid >> 5;

    if (tid == 0) s_vbid = (int)atomicAdd(&g_ticket, 1u);
    __syncthreads();
    int vbid = s_vbid;
    int i = vbid * 256 + tid;

    int val = (i < n) ? g_cnt[i] : 0;
    int x = val;
#pragma unroll
    for (int o = 1; o < 32; o <<= 1) {
        int t = __shfl_up_sync(0xFFFFFFFFu, x, o);
        if (lane >= o) x += t;
    }
    if (lane == 31) wsum[w] = x;
    __syncthreads();
    if (tid < 8) {
        int ws = wsum[tid];
        int y = ws;
#pragma unroll
        for (int o = 1; o < 8; o <<= 1) {
            int t = __shfl_up_sync(0xFFu, y, o);
            if (tid >= o) y += t;
        }
        woff[tid] = y - ws;
        if (tid == 7) wsum[0] = y;   // block aggregate (after this sync point)
    }
    __syncthreads();
    int incl = woff[w] + x;          // inclusive within block
    int agg = wsum[0];

    if (tid == 0) {
        if (vbid == 0) {
            atomicExch(&g_status[0], (2ULL << 32) | (unsigned long long)(unsigned)agg);
            s_excl = 0;
        } else {
            atomicExch(&g_status[vbid], (1ULL << 32) | (unsigned long long)(unsigned)agg);
            int sum = 0;
            int p = vbid - 1;
            while (true) {
                unsigned long long s = atomicAdd(&g_status[p], 0ULL);
                unsigned flag = (unsigned)(s >> 32);
                if (flag == 0u) continue;
                sum += (int)(unsigned)s;
                if (flag == 2u) break;
                p--;
            }
            atomicExch(&g_status[vbid], (2ULL << 32) | (unsigned long long)(unsigned)(sum + agg));
            s_excl = sum;
        }
    }
    __syncthreads();
    int base = s_excl;

    if (i < n) {
        int excl = base + incl - val;
        g_rowptr[i] = excl;
        g_cursor[i] = excl;
        g_dinv[i] = rsqrtf((float)val + 1.0f);
        if (i == n - 1) g_rowptr[n] = base + incl;
    }
}

__global__ void k_fill(const int* __restrict__ ei, int e) {
    int i = blockIdx.x * blockDim.x + threadIdx.x;
    if (i < e) {
        int d = ei[e + i];
        int p = atomicAdd(&g_cursor[d], 1);
        g_csr[p] = ei[i];
    }
}

// ---------------- fp16 gather core ------------------------------------------
// one warp per node; lane = 4 consecutive halves (uint2=8B). Indices and
// weights prefetched cooperatively per 32-edge chunk; inner loop issues 4
// independent row loads per step.
__device__ __forceinline__ float4 agg_gather(const __half* __restrict__ X,
                                             int node, int lane, float di) {
    const uint2* x2 = (const uint2*)X;   // 32 uint2 per row
    uint2 sr = __ldg(&x2[(size_t)node * 32 + lane]);
    float2 f01 = __half22float2(*(__half2*)&sr.x);
    float2 f23 = __half22float2(*(__half2*)&sr.y);
    float4 acc = make_float4(di * f01.x, di * f01.y, di * f23.x, di * f23.y);

    int s0 = __ldg(&g_rowptr[node]), s1 = __ldg(&g_rowptr[node + 1]);

#define AG_STEP(ii, ww) {                                                      \
        uint2 r = __ldg(&x2[(size_t)(ii) * 32 + lane]);                        \
        float2 a = __half22float2(*(__half2*)&r.x);                            \
        float2 b = __half22float2(*(__half2*)&r.y);                            \
        acc.x += (ww) * a.x; acc.y += (ww) * a.y;                              \
        acc.z += (ww) * b.x; acc.w += (ww) * b.y; }

    for (int base = s0; base < s1; base += 32) {
        int m = s1 - base; if (m > 32) m = 32;
        int li = base + ((lane < m) ? lane : 0);
        int idx = __ldg(&g_csr[li]);
        float wv = __ldg(&g_dinv[idx]);
        int j = 0;
        for (; j + 4 <= m; j += 4) {
            int i0 = __shfl_sync(0xFFFFFFFFu, idx, j);
            int i1 = __shfl_sync(0xFFFFFFFFu, idx, j + 1);
            int i2 = __shfl_sync(0xFFFFFFFFu, idx, j + 2);
            int i3 = __shfl_sync(0xFFFFFFFFu, idx, j + 3);
            float w0 = __shfl_sync(0xFFFFFFFFu, wv, j);
            float w1 = __shfl_sync(0xFFFFFFFFu, wv, j + 1);
            float w2 = __shfl_sync(0xFFFFFFFFu, wv, j + 2);
            float w3 = __shfl_sync(0xFFFFFFFFu, wv, j + 3);
            AG_STEP(i0, w0); AG_STEP(i1, w1); AG_STEP(i2, w2); AG_STEP(i3, w3);
        }
        for (; j < m; j++) {
            int i0 = __shfl_sync(0xFFFFFFFFu, idx, j);
            float w0 = __shfl_sync(0xFFFFFFFFu, wv, j);
            AG_STEP(i0, w0);
        }
    }
#undef AG_STEP
    acc.x *= di; acc.y *= di; acc.z *= di; acc.w *= di;
    return acc;
}

// ---- agg1: h = Agg(U) + b1  (fp16 in, fp32 out) ----------------------------
__global__ void k_agg_bias(const __half* __restrict__ X, float* __restrict__ Y,
                           const float* __restrict__ bias, int n) {
    int gw = (blockIdx.x * blockDim.x + threadIdx.x) >> 5;
    int lane = threadIdx.x & 31;
    if (gw >= n) return;
    float di = __ldg(&g_dinv[gw]);
    float4 acc = agg_gather(X, gw, lane, di);
    float4 b = __ldg((const float4*)&bias[lane * 4]);
    acc.x += b.x; acc.y += b.y; acc.z += b.z; acc.w += b.w;
    ((float4*)Y)[(size_t)gw * 32 + lane] = acc;
}

// ---- agg2: [mu|ls] = Agg(V)+bias; out = mu + init*exp(ls) ------------------
__global__ void k_agg_out(const __half* __restrict__ X,
                          const float* __restrict__ bmu, const float* __restrict__ bls,
                          const float* __restrict__ initd,
                          float* __restrict__ out, int n) {
    int gw = (blockIdx.x * blockDim.x + threadIdx.x) >> 5;
    int lane = threadIdx.x & 31;
    if (gw >= n) return;
    float di = __ldg(&g_dinv[gw]);
    float4 v = agg_gather(X, gw, lane, di);
    float4 b = (lane < 16) ? __ldg((const float4*)&bmu[lane * 4])
                           : __ldg((const float4*)&bls[lane * 4 - 64]);
    v.x += b.x; v.y += b.y; v.z += b.z; v.w += b.w;
    float4 p;
    p.x = __shfl_xor_sync(0xFFFFFFFFu, v.x, 16);
    p.y = __shfl_xor_sync(0xFFFFFFFFu, v.y, 16);
    p.z = __shfl_xor_sync(0xFFFFFFFFu, v.z, 16);
    p.w = __shfl_xor_sync(0xFFFFFFFFu, v.w, 16);
    if (lane < 16) {
        float4 ini = __ldg((const float4*)&initd[(size_t)gw * 64 + lane * 4]);
        float4 o;
        o.x = v.x + ini.x * expf(p.x);
        o.y = v.y + ini.y * expf(p.y);
        o.z = v.z + ini.z * expf(p.z);
        o.w = v.w + ini.w * expf(p.w);
        *(float4*)&out[(size_t)gw * 64 + lane * 4] = o;
    }
}

// ================= mma.sync split-bf16 GEMM (fp16 out) ======================
// C[n,128] = A[n,128] @ [Wa|Wb](128x128); optional fused edge-count prologue.
#define KS_B 136
#define SOFF_BH 0
#define SOFF_BL (128 * KS_B * 2)
#define SMEM_MMA (SOFF_BL + 128 * KS_B * 2)

__device__ __forceinline__ void split2(float a, float b, uint32_t& hi, uint32_t& lo) {
    __nv_bfloat16 ah = __float2bfloat16(a), bh = __float2bfloat16(b);
    float ar = a - __bfloat162float(ah);
    float br = b - __bfloat162float(bh);
    __nv_bfloat16 al = __float2bfloat16(ar), bl = __float2bfloat16(br);
    __nv_bfloat162 h; h.x = ah; h.y = bh;
    __nv_bfloat162 l; l.x = al; l.y = bl;
    hi = *(uint32_t*)&h;
    lo = *(uint32_t*)&l;
}

__device__ __forceinline__ uint32_t smem_u32(const void* p) {
    uint32_t a;
    asm("{ .reg .u64 t; cvta.to.shared.u64 t, %1; cvt.u32.u64 %0, t; }" : "=r"(a) : "l"(p));
    return a;
}

__device__ __forceinline__ void mma16816(float& c0, float& c1, float& c2, float& c3,
                                         uint32_t a0, uint32_t a1, uint32_t a2, uint32_t a3,
                                         uint32_t b0, uint32_t b1) {
    asm volatile(
        "mma.sync.aligned.m16n8k16.row.col.f32.bf16.bf16.f32 "
        "{%0,%1,%2,%3}, {%4,%5,%6,%7}, {%8,%9}, {%0,%1,%2,%3};"
        : "+f"(c0), "+f"(c1), "+f"(c2), "+f"(c3)
        : "r"(a0), "r"(a1), "r"(a2), "r"(a3), "r"(b0), "r"(b1));
}

__device__ __forceinline__ void ldsm_x2(uint32_t& r0, uint32_t& r1, uint32_t addr) {
    asm volatile("ldmatrix.sync.aligned.m8n8.x2.shared.b16 {%0, %1}, [%2];"
        : "=r"(r0), "=r"(r1) : "r"(addr));
}

__global__ void __launch_bounds__(256)
k_mma_gemm(const float* __restrict__ A,
           const float* __restrict__ Wa, int Na,
           const float* __restrict__ Wb,
           __half* __restrict__ C, int n,
           const int* __restrict__ ei, int e) {
    extern __shared__ char smem[];
    uint16_t* BH = (uint16_t*)(smem + SOFF_BH);
    uint16_t* BL = (uint16_t*)(smem + SOFF_BL);
    int tid = threadIdx.x;
    int wid = tid >> 5, lane = tid & 31;
    int row0 = blockIdx.x * 128;
    int Nb = 128 - Na;

    // ---- fused degree count (independent of GEMM) --------------------------
    if (ei) {
        int stride = gridDim.x * blockDim.x;
        for (int i = blockIdx.x * blockDim.x + tid; i < e; i += stride)
            atomicAdd(&g_cnt[__ldg(&ei[e + i])], 1);
    }

    // ---- B = W^T into smem (hi/lo), [n][k] padded stride 136 ---------------
    {
        int col = tid >> 1;
        int kbeg = (tid & 1) * 64;
        const float* Wcol = (col < Na) ? (Wa + col) : (Wb + (col - Na));
        int stride = (col < Na) ? Na : Nb;
#pragma unroll 8
        for (int k = kbeg; k < kbeg + 64; k++) {
            float w = __ldg(&Wcol[k * stride]);
            __nv_bfloat16 wh = __float2bfloat16(w);
            float wr = w - __bfloat162float(wh);
            __nv_bfloat16 wl = __float2bfloat16(wr);
            BH[col * KS_B + k] = *(uint16_t*)&wh;
            BL[col * KS_B + k] = *(uint16_t*)&wl;
        }
    }

    // ---- A fragments from gmem (split hi/lo into regs) ---------------------
    int rbase = row0 + wid * 16;
    int r0 = rbase + (lane >> 2);
    int r1 = r0 + 8;
    int r0c = (r0 < n) ? r0 : 0;
    int r1c = (r1 < n) ? r1 : 0;
    const float* A0 = A + (size_t)r0c * 128;
    const float* A1 = A + (size_t)r1c * 128;
    int cc = (lane & 3) * 2;

    uint32_t aH[8][4], aL[8][4];
#pragma unroll
    for (int ks = 0; ks < 8; ks++) {
        int k0 = ks * 16;
        float2 v00 = __ldg((const float2*)&A0[k0 + cc]);
        float2 v10 = __ldg((const float2*)&A1[k0 + cc]);
        float2 v02 = __ldg((const float2*)&A0[k0 + cc + 8]);
        float2 v12 = __ldg((const float2*)&A1[k0 + cc + 8]);
        split2(v00.x, v00.y, aH[ks][0], aL[ks][0]);
        split2(v10.x, v10.y, aH[ks][1], aL[ks][1]);
        split2(v02.x, v02.y, aH[ks][2], aL[ks][2]);
        split2(v12.x, v12.y, aH[ks][3], aL[ks][3]);
    }

    __syncthreads();

    uint32_t bh_base = smem_u32(BH);
    uint32_t bl_base = smem_u32(BL);
    uint32_t lrow = (uint32_t)(lane & 7);
    uint32_t khalf = ((uint32_t)(lane >> 3) & 1) * 8;

    bool w0 = (r0 < n), w1 = (r1 < n);
    __half* C0 = C + (size_t)r0c * 128;
    __half* C1 = C + (size_t)r1c * 128;

#pragma unroll 2
    for (int nb = 0; nb < 16; nb++) {
        int n0 = nb * 8;
        uint32_t off = ((n0 + lrow) * KS_B + khalf) * 2;
        uint32_t adH = bh_base + off;
        uint32_t adL = bl_base + off;
        float c0 = 0.f, c1 = 0.f, c2 = 0.f, c3 = 0.f;
#pragma unroll
        for (int ks = 0; ks < 8; ks++) {
            uint32_t bh0, bh1, bl0, bl1;
            ldsm_x2(bh0, bh1, adH + ks * 32);
            ldsm_x2(bl0, bl1, adL + ks * 32);
            mma16816(c0, c1, c2, c3, aH[ks][0], aH[ks][1], aH[ks][2], aH[ks][3], bh0, bh1);
            mma16816(c0, c1, c2, c3, aH[ks][0], aH[ks][1], aH[ks][2], aH[ks][3], bl0, bl1);
            mma16816(c0, c1, c2, c3, aL[ks][0], aL[ks][1], aL[ks][2], aL[ks][3], bh0, bh1);
        }
        if (w0) *(__half2*)&C0[n0 + cc] = __floats2half2_rn(c0, c1);
        if (w1) *(__half2*)&C1[n0 + cc] = __floats2half2_rn(c2, c3);
    }
}

// ---------------- launch ----------------------------------------------------
extern "C" void kernel_launch(void* const* d_in, const int* in_sizes, int n_in,
                              void* d_out, int out_size) {
    const float* x    = (const float*)d_in[0];
    const int*   ei   = (const int*)d_in[1];
    const float* initd= (const float*)d_in[2];
    const float* W1   = (const float*)d_in[3];
    const float* b1   = (const float*)d_in[4];
    const float* Wmu  = (const float*)d_in[5];
    const float* bmu  = (const float*)d_in[6];
    const float* Wls  = (const float*)d_in[7];
    const float* bls  = (const float*)d_in[8];
    float* out = (float*)d_out;

    int n = in_sizes[0] / FD;
    int e = in_sizes[1] / 2;

    void *pH = nullptr, *pA = nullptr;
    cudaGetSymbolAddress(&pH, g_bufH);
    cudaGetSymbolAddress(&pA, g_bufA);
    __half* bufH = (__half*)pH;
    float*  bufA = (float*)pA;

    cudaFuncSetAttribute(k_mma_gemm, cudaFuncAttributeMaxDynamicSharedMemorySize, SMEM_MMA);

    int agg_grid = (n * 32 + 255) / 256;
    int gemm_grid = (n + 127) / 128;
    int scan_grid = (n + 255) / 256;

    // zero degree counters + lookback state
    k_zero<<<(n + 255) / 256, 256>>>(n);

    // layer-1 GEMM with fused degree count: U = x @ W1 (fp16)
    k_mma_gemm<<<gemm_grid, 256, SMEM_MMA>>>(x, W1, 128, W1, bufH, n, ei, e);

    // CSR: single-pass scan (rowptr/cursor/dinv), then fill
    k_scan_lb<<<scan_grid, 256>>>(n);
    k_fill<<<(e + 255) / 256, 256>>>(ei, e);

    // h = Agg(U) + b1 (fp32)
    k_agg_bias<<<agg_grid, 256>>>(bufH, bufA, b1, n);

    // layer 2: V = h @ [Wmu|Wls] (fp16); out = Agg(V)+bias, reparametrized
    k_mma_gemm<<<gemm_grid, 256, SMEM_MMA>>>(bufA, Wmu, 64, Wls, bufH, n, nullptr, 0);
    k_agg_out<<<agg_grid, 256>>>(bufH, bmu, bls, initd, out, n);
}

// round 7
// speedup vs baseline: 1.0555x; 1.0555x over previous
#include <cuda_runtime.h>
#include <cuda_fp16.h>
#include <cuda_bf16.h>
#include <cstdint>
#include <math.h>

#define MAXN 100000
#define MAXE 1600000
#define FD   128      // IN == HID == 128
#define OUTC 64

// ---------------- scratch (device globals; no allocation allowed) ----------
__device__ __half g_bufH[MAXN * FD];  // fp16 GEMM outputs (U, then V)
__device__ float  g_bufA[MAXN * FD];  // fp32 h (layer-1 output)
__device__ int    g_cnt[MAXN];
__device__ int    g_rowptr[MAXN + 1];
__device__ int    g_cursor[MAXN];
__device__ int2   g_csrw[MAXE];       // (src index, dinv[src] bits)
__device__ float  g_dinv[MAXN];
__device__ unsigned long long g_status[512];   // lookback: (flag<<32)|value
__device__ unsigned int g_ticket;

// ---------------- zero / init ----------------------------------------------
__global__ void k_zero(int n) {
    int i = blockIdx.x * blockDim.x + threadIdx.x;
    if (i < n) g_cnt[i] = 0;
    if (i < 512) g_status[i] = 0ULL;
    if (i == 0) g_ticket = 0u;
}

// ---------------- single-pass scan (decoupled lookback) ---------------------
__global__ void k_scan_lb(int n) {
    __shared__ int s_vbid;
    __shared__ int s_excl;
    __shared__ int wsum[8], woff[8];
    int tid = threadIdx.x, lane = tid & 31, w = tid >> 5;

    if (tid == 0) s_vbid = (int)atomicAdd(&g_ticket, 1u);
    __syncthreads();
    int vbid = s_vbid;
    int i = vbid * 256 + tid;

    int val = (i < n) ? g_cnt[i] : 0;
    int x = val;
#pragma unroll
    for (int o = 1; o < 32; o <<= 1) {
        int t = __shfl_up_sync(0xFFFFFFFFu, x, o);
        if (lane >= o) x += t;
    }
    if (lane == 31) wsum[w] = x;
    __syncthreads();
    if (tid < 8) {
        int ws = wsum[tid];
        int y = ws;
#pragma unroll
        for (int o = 1; o < 8; o <<= 1) {
            int t = __shfl_up_sync(0xFFu, y, o);
            if (tid >= o) y += t;
        }
        woff[tid] = y - ws;
        if (tid == 7) wsum[0] = y;
    }
    __syncthreads();
    int incl = woff[w] + x;
    int agg = wsum[0];

    if (tid == 0) {
        if (vbid == 0) {
            atomicExch(&g_status[0], (2ULL << 32) | (unsigned long long)(unsigned)agg);
            s_excl = 0;
        } else {
            atomicExch(&g_status[vbid], (1ULL << 32) | (unsigned long long)(unsigned)agg);
            int sum = 0;
            int p = vbid - 1;
            while (true) {
                unsigned long long s = atomicAdd(&g_status[p], 0ULL);
                unsigned flag = (unsigned)(s >> 32);
                if (flag == 0u) continue;
                sum += (int)(unsigned)s;
                if (flag == 2u) break;
                p--;
            }
            atomicExch(&g_status[vbid], (2ULL << 32) | (unsigned long long)(unsigned)(sum + agg));
            s_excl = sum;
        }
    }
    __syncthreads();
    int base = s_excl;

    if (i < n) {
        int excl = base + incl - val;
        g_rowptr[i] = excl;
        g_cursor[i] = excl;
        g_dinv[i] = rsqrtf((float)val + 1.0f);
        if (i == n - 1) g_rowptr[n] = base + incl;
    }
}

// ---------------- CSR fill with fused weight --------------------------------
__global__ void k_fill(const int* __restrict__ ei, int e) {
    int i = blockIdx.x * blockDim.x + threadIdx.x;
    if (i < e) {
        int d = ei[e + i];
        int s = ei[i];
        float w = __ldg(&g_dinv[s]);
        int p = atomicAdd(&g_cursor[d], 1);
        g_csrw[p] = make_int2(s, __float_as_int(w));
    }
}

// ---------------- fp16 gather core ------------------------------------------
// one warp per node; lane = 4 consecutive halves (uint2=8B).
// (src, weight) pairs in CSR; 4-wide unroll -> 4 independent pair loads +
// 4 independent row loads in flight.
__device__ __forceinline__ float4 agg_gather(const __half* __restrict__ X,
                                             int node, int lane, float di) {
    const uint2* x2 = (const uint2*)X;   // 32 uint2 per row
    uint2 sr = __ldg(&x2[(size_t)node * 32 + lane]);
    float2 f01 = __half22float2(*(__half2*)&sr.x);
    float2 f23 = __half22float2(*(__half2*)&sr.y);
    float4 acc = make_float4(di * f01.x, di * f01.y, di * f23.x, di * f23.y);

    int s0 = __ldg(&g_rowptr[node]), s1 = __ldg(&g_rowptr[node + 1]);

#define AG_STEP(pp) {                                                          \
        float ww = __int_as_float((pp).y);                                     \
        uint2 r = __ldg(&x2[(size_t)(pp).x * 32 + lane]);                      \
        float2 a = __half22float2(*(__half2*)&r.x);                            \
        float2 b = __half22float2(*(__half2*)&r.y);                            \
        acc.x += ww * a.x; acc.y += ww * a.y;                                  \
        acc.z += ww * b.x; acc.w += ww * b.y; }

    int e = s0;
    for (; e + 4 <= s1; e += 4) {
        int2 p0 = __ldg(&g_csrw[e]);
        int2 p1 = __ldg(&g_csrw[e + 1]);
        int2 p2 = __ldg(&g_csrw[e + 2]);
        int2 p3 = __ldg(&g_csrw[e + 3]);
        AG_STEP(p0); AG_STEP(p1); AG_STEP(p2); AG_STEP(p3);
    }
    for (; e < s1; e++) {
        int2 p = __ldg(&g_csrw[e]);
        AG_STEP(p);
    }
#undef AG_STEP
    acc.x *= di; acc.y *= di; acc.z *= di; acc.w *= di;
    return acc;
}

// ---- agg1: h = Agg(U) + b1  (fp16 in, fp32 out) ----------------------------
__global__ void k_agg_bias(const __half* __restrict__ X, float* __restrict__ Y,
                           const float* __restrict__ bias, int n) {
    int gw = (blockIdx.x * blockDim.x + threadIdx.x) >> 5;
    int lane = threadIdx.x & 31;
    if (gw >= n) return;
    float di = __ldg(&g_dinv[gw]);
    float4 acc = agg_gather(X, gw, lane, di);
    float4 b = __ldg((const float4*)&bias[lane * 4]);
    acc.x += b.x; acc.y += b.y; acc.z += b.z; acc.w += b.w;
    ((float4*)Y)[(size_t)gw * 32 + lane] = acc;
}

// ---- agg2: [mu|ls] = Agg(V)+bias; out = mu + init*exp(ls) ------------------
__global__ void k_agg_out(const __half* __restrict__ X,
                          const float* __restrict__ bmu, const float* __restrict__ bls,
                          const float* __restrict__ initd,
                          float* __restrict__ out, int n) {
    int gw = (blockIdx.x * blockDim.x + threadIdx.x) >> 5;
    int lane = threadIdx.x & 31;
    if (gw >= n) return;
    float di = __ldg(&g_dinv[gw]);
    float4 v = agg_gather(X, gw, lane, di);
    float4 b = (lane < 16) ? __ldg((const float4*)&bmu[lane * 4])
                           : __ldg((const float4*)&bls[lane * 4 - 64]);
    v.x += b.x; v.y += b.y; v.z += b.z; v.w += b.w;
    float4 p;
    p.x = __shfl_xor_sync(0xFFFFFFFFu, v.x, 16);
    p.y = __shfl_xor_sync(0xFFFFFFFFu, v.y, 16);
    p.z = __shfl_xor_sync(0xFFFFFFFFu, v.z, 16);
    p.w = __shfl_xor_sync(0xFFFFFFFFu, v.w, 16);
    if (lane < 16) {
        float4 ini = __ldg((const float4*)&initd[(size_t)gw * 64 + lane * 4]);
        float4 o;
        o.x = v.x + ini.x * expf(p.x);
        o.y = v.y + ini.y * expf(p.y);
        o.z = v.z + ini.z * expf(p.z);
        o.w = v.w + ini.w * expf(p.w);
        *(float4*)&out[(size_t)gw * 64 + lane * 4] = o;
    }
}

// ================= mma.sync split-bf16 GEMM (fp16 out) ======================
#define KS_B 136
#define SOFF_BH 0
#define SOFF_BL (128 * KS_B * 2)
#define SMEM_MMA (SOFF_BL + 128 * KS_B * 2)

__device__ __forceinline__ void split2(float a, float b, uint32_t& hi, uint32_t& lo) {
    __nv_bfloat16 ah = __float2bfloat16(a), bh = __float2bfloat16(b);
    float ar = a - __bfloat162float(ah);
    float br = b - __bfloat162float(bh);
    __nv_bfloat16 al = __float2bfloat16(ar), bl = __float2bfloat16(br);
    __nv_bfloat162 h; h.x = ah; h.y = bh;
    __nv_bfloat162 l; l.x = al; l.y = bl;
    hi = *(uint32_t*)&h;
    lo = *(uint32_t*)&l;
}

__device__ __forceinline__ uint32_t smem_u32(const void* p) {
    uint32_t a;
    asm("{ .reg .u64 t; cvta.to.shared.u64 t, %1; cvt.u32.u64 %0, t; }" : "=r"(a) : "l"(p));
    return a;
}

__device__ __forceinline__ void mma16816(float& c0, float& c1, float& c2, float& c3,
                                         uint32_t a0, uint32_t a1, uint32_t a2, uint32_t a3,
                                         uint32_t b0, uint32_t b1) {
    asm volatile(
        "mma.sync.aligned.m16n8k16.row.col.f32.bf16.bf16.f32 "
        "{%0,%1,%2,%3}, {%4,%5,%6,%7}, {%8,%9}, {%0,%1,%2,%3};"
        : "+f"(c0), "+f"(c1), "+f"(c2), "+f"(c3)
        : "r"(a0), "r"(a1), "r"(a2), "r"(a3), "r"(b0), "r"(b1));
}

__device__ __forceinline__ void ldsm_x2(uint32_t& r0, uint32_t& r1, uint32_t addr) {
    asm volatile("ldmatrix.sync.aligned.m8n8.x2.shared.b16 {%0, %1}, [%2];"
        : "=r"(r0), "=r"(r1) : "r"(addr));
}

__global__ void __launch_bounds__(256)
k_mma_gemm(const float* __restrict__ A,
           const float* __restrict__ Wa, int Na,
           const float* __restrict__ Wb,
           __half* __restrict__ C, int n,
           const int* __restrict__ ei, int e) {
    extern __shared__ char smem[];
    uint16_t* BH = (uint16_t*)(smem + SOFF_BH);
    uint16_t* BL = (uint16_t*)(smem + SOFF_BL);
    int tid = threadIdx.x;
    int wid = tid >> 5, lane = tid & 31;
    int row0 = blockIdx.x * 128;
    int Nb = 128 - Na;

    // ---- fused degree count (independent of GEMM) --------------------------
    if (ei) {
        int stride = gridDim.x * blockDim.x;
        for (int i = blockIdx.x * blockDim.x + tid; i < e; i += stride)
            atomicAdd(&g_cnt[__ldg(&ei[e + i])], 1);
    }

    // ---- B = W^T into smem (hi/lo), [n][k] padded stride 136 ---------------
    {
        int col = tid >> 1;
        int kbeg = (tid & 1) * 64;
        const float* Wcol = (col < Na) ? (Wa + col) : (Wb + (col - Na));
        int stride = (col < Na) ? Na : Nb;
#pragma unroll 8
        for (int k = kbeg; k < kbeg + 64; k++) {
            float w = __ldg(&Wcol[k * stride]);
            __nv_bfloat16 wh = __float2bfloat16(w);
            float wr = w - __bfloat162float(wh);
            __nv_bfloat16 wl = __float2bfloat16(wr);
            BH[col * KS_B + k] = *(uint16_t*)&wh;
            BL[col * KS_B + k] = *(uint16_t*)&wl;
        }
    }

    // ---- A fragments from gmem (split hi/lo into regs) ---------------------
    int rbase = row0 + wid * 16;
    int r0 = rbase + (lane >> 2);
    int r1 = r0 + 8;
    int r0c = (r0 < n) ? r0 : 0;
    int r1c = (r1 < n) ? r1 : 0;
    const float* A0 = A + (size_t)r0c * 128;
    const float* A1 = A + (size_t)r1c * 128;
    int cc = (lane & 3) * 2;

    uint32_t aH[8][4], aL[8][4];
#pragma unroll
    for (int ks = 0; ks < 8; ks++) {
        int k0 = ks * 16;
        float2 v00 = __ldg((const float2*)&A0[k0 + cc]);
        float2 v10 = __ldg((const float2*)&A1[k0 + cc]);
        float2 v02 = __ldg((const float2*)&A0[k0 + cc + 8]);
        float2 v12 = __ldg((const float2*)&A1[k0 + cc + 8]);
        split2(v00.x, v00.y, aH[ks][0], aL[ks][0]);
        split2(v10.x, v10.y, aH[ks][1], aL[ks][1]);
        split2(v02.x, v02.y, aH[ks][2], aL[ks][2]);
        split2(v12.x, v12.y, aH[ks][3], aL[ks][3]);
    }

    __syncthreads();

    uint32_t bh_base = smem_u32(BH);
    uint32_t bl_base = smem_u32(BL);
    uint32_t lrow = (uint32_t)(lane & 7);
    uint32_t khalf = ((uint32_t)(lane >> 3) & 1) * 8;

    bool w0 = (r0 < n), w1 = (r1 < n);
    __half* C0 = C + (size_t)r0c * 128;
    __half* C1 = C + (size_t)r1c * 128;

#pragma unroll 2
    for (int nb = 0; nb < 16; nb++) {
        int n0 = nb * 8;
        uint32_t off = ((n0 + lrow) * KS_B + khalf) * 2;
        uint32_t adH = bh_base + off;
        uint32_t adL = bl_base + off;
        float c0 = 0.f, c1 = 0.f, c2 = 0.f, c3 = 0.f;
#pragma unroll
        for (int ks = 0; ks < 8; ks++) {
            uint32_t bh0, bh1, bl0, bl1;
            ldsm_x2(bh0, bh1, adH + ks * 32);
            ldsm_x2(bl0, bl1, adL + ks * 32);
            mma16816(c0, c1, c2, c3, aH[ks][0], aH[ks][1], aH[ks][2], aH[ks][3], bh0, bh1);
            mma16816(c0, c1, c2, c3, aH[ks][0], aH[ks][1], aH[ks][2], aH[ks][3], bl0, bl1);
            mma16816(c0, c1, c2, c3, aL[ks][0], aL[ks][1], aL[ks][2], aL[ks][3], bh0, bh1);
        }
        if (w0) *(__half2*)&C0[n0 + cc] = __floats2half2_rn(c0, c1);
        if (w1) *(__half2*)&C1[n0 + cc] = __floats2half2_rn(c2, c3);
    }
}

// ---------------- launch ----------------------------------------------------
extern "C" void kernel_launch(void* const* d_in, const int* in_sizes, int n_in,
                              void* d_out, int out_size) {
    const float* x    = (const float*)d_in[0];
    const int*   ei   = (const int*)d_in[1];
    const float* initd= (const float*)d_in[2];
    const float* W1   = (const float*)d_in[3];
    const float* b1   = (const float*)d_in[4];
    const float* Wmu  = (const float*)d_in[5];
    const float* bmu  = (const float*)d_in[6];
    const float* Wls  = (const float*)d_in[7];
    const float* bls  = (const float*)d_in[8];
    float* out = (float*)d_out;

    int n = in_sizes[0] / FD;
    int e = in_sizes[1] / 2;

    void *pH = nullptr, *pA = nullptr;
    cudaGetSymbolAddress(&pH, g_bufH);
    cudaGetSymbolAddress(&pA, g_bufA);
    __half* bufH = (__half*)pH;
    float*  bufA = (float*)pA;

    cudaFuncSetAttribute(k_mma_gemm, cudaFuncAttributeMaxDynamicSharedMemorySize, SMEM_MMA);

    int agg_grid = (n * 32 + 255) / 256;
    int gemm_grid = (n + 127) / 128;
    int scan_grid = (n + 255) / 256;

    // zero degree counters + lookback state
    k_zero<<<(n + 255) / 256, 256>>>(n);

    // layer-1 GEMM with fused degree count: U = x @ W1 (fp16)
    k_mma_gemm<<<gemm_grid, 256, SMEM_MMA>>>(x, W1, 128, W1, bufH, n, ei, e);

    // CSR: single-pass scan (rowptr/cursor/dinv), then weighted fill
    k_scan_lb<<<scan_grid, 256>>>(n);
    k_fill<<<(e + 255) / 256, 256>>>(ei, e);

    // h = Agg(U) + b1 (fp32)
    k_agg_bias<<<agg_grid, 256>>>(bufH, bufA, b1, n);

    // layer 2: V = h @ [Wmu|Wls] (fp16); out = Agg(V)+bias, reparametrized
    k_mma_gemm<<<gemm_grid, 256, SMEM_MMA>>>(bufA, Wmu, 64, Wls, bufH, n, nullptr, 0);
    k_agg_out<<<agg_grid, 256>>>(bufH, bmu, bls, initd, out, n);
}